// round 2
// baseline (speedup 1.0000x reference)
#include <cuda_runtime.h>
#include <cstdint>

// Problem constants
#define S_LEN 4096
#define HID   768
#define NHEAD 12
#define DH    64

// Scratch: Q/K/V in head-major layout [H][S][DH], fp32. 3 x 12.6 MB.
__device__ float g_QKV[3][NHEAD * S_LEN * DH];

// ---------------------------------------------------------------------------
// tf32 helpers
// ---------------------------------------------------------------------------
__device__ __forceinline__ uint32_t f2tf32(float x) {
    uint32_t y;
    asm volatile("cvt.rna.tf32.f32 %0, %1;" : "=r"(y) : "f"(x));
    return y;
}

__device__ __forceinline__ void mma_tf32(float* c, const uint32_t* a, const uint32_t* b) {
    asm volatile(
        "mma.sync.aligned.m16n8k8.row.col.f32.tf32.tf32.f32 "
        "{%0,%1,%2,%3}, {%4,%5,%6,%7}, {%8,%9}, {%0,%1,%2,%3};\n"
        : "+f"(c[0]), "+f"(c[1]), "+f"(c[2]), "+f"(c[3])
        : "r"(a[0]), "r"(a[1]), "r"(a[2]), "r"(a[3]), "r"(b[0]), "r"(b[1]));
}

// ---------------------------------------------------------------------------
// Kernel 1: QKV projection.  C[4096,768] = X @ W^T + b  for W in {Wq,Wk,Wv}.
// C[m,n] = sum_k X[m,k] * W[n,k].  Output written head-major into g_QKV.
// Tile: BM=128, BN=64 (== one head), BK=32; 256 threads, 8 warps (4x2).
// ---------------------------------------------------------------------------
__global__ __launch_bounds__(256) void qkv_gemm_kernel(
    const float* __restrict__ x,
    const float* __restrict__ Wq, const float* __restrict__ bq,
    const float* __restrict__ Wk, const float* __restrict__ bk,
    const float* __restrict__ Wv, const float* __restrict__ bv)
{
    const int tm  = blockIdx.x;   // 0..31  (M tiles of 128)
    const int tn  = blockIdx.y;   // 0..11  (head == N tile of 64)
    const int mat = blockIdx.z;   // 0=Q 1=K 2=V

    const float* W    = (mat == 0) ? Wq : (mat == 1) ? Wk : Wv;
    const float* bias = (mat == 0) ? bq : (mat == 1) ? bk : bv;
    float* out = &g_QKV[mat][tn * S_LEN * DH];

    __shared__ float Xs[128][36];  // [m][k], pad 4 -> conflict-free frag loads
    __shared__ float Ws[64][36];   // [n][k]

    const int tid  = threadIdx.x;
    const int lane = tid & 31;
    const int warp = tid >> 5;
    const int wm   = warp >> 1;    // 0..3
    const int wn   = warp & 1;     // 0..1

    float acc[2][4][4];
    #pragma unroll
    for (int i = 0; i < 2; i++)
        #pragma unroll
        for (int j = 0; j < 4; j++)
            #pragma unroll
            for (int k = 0; k < 4; k++) acc[i][j][k] = 0.f;

    for (int kt = 0; kt < HID; kt += 32) {
        // Load X tile 128x32 (1024 float4)
        #pragma unroll
        for (int i = 0; i < 4; i++) {
            int linear = tid + i * 256;
            int r = linear >> 3, c4 = (linear & 7) << 2;
            float4 v = *reinterpret_cast<const float4*>(&x[(tm * 128 + r) * HID + kt + c4]);
            *reinterpret_cast<float4*>(&Xs[r][c4]) = v;
        }
        // Load W tile 64x32 (512 float4)
        #pragma unroll
        for (int i = 0; i < 2; i++) {
            int linear = tid + i * 256;
            int r = linear >> 3, c4 = (linear & 7) << 2;
            float4 v = *reinterpret_cast<const float4*>(&W[(tn * 64 + r) * HID + kt + c4]);
            *reinterpret_cast<float4*>(&Ws[r][c4]) = v;
        }
        __syncthreads();

        #pragma unroll
        for (int kk = 0; kk < 32; kk += 8) {
            uint32_t a[2][4], b[4][2];
            #pragma unroll
            for (int im = 0; im < 2; im++) {
                int r0 = wm * 32 + im * 16 + (lane >> 2);
                int c0 = kk + (lane & 3);
                a[im][0] = f2tf32(Xs[r0][c0]);
                a[im][1] = f2tf32(Xs[r0 + 8][c0]);
                a[im][2] = f2tf32(Xs[r0][c0 + 4]);
                a[im][3] = f2tf32(Xs[r0 + 8][c0 + 4]);
            }
            #pragma unroll
            for (int in_ = 0; in_ < 4; in_++) {
                int n0 = wn * 32 + in_ * 8 + (lane >> 2);
                int c0 = kk + (lane & 3);
                b[in_][0] = f2tf32(Ws[n0][c0]);
                b[in_][1] = f2tf32(Ws[n0][c0 + 4]);
            }
            #pragma unroll
            for (int im = 0; im < 2; im++)
                #pragma unroll
                for (int in_ = 0; in_ < 4; in_++)
                    mma_tf32(acc[im][in_], a[im], b[in_]);
        }
        __syncthreads();
    }

    // Epilogue: add bias, write head-major scratch [s][d]
    #pragma unroll
    for (int im = 0; im < 2; im++) {
        #pragma unroll
        for (int in_ = 0; in_ < 4; in_++) {
            int row = tm * 128 + wm * 32 + im * 16 + (lane >> 2);
            int d   = wn * 32 + in_ * 8 + ((lane & 3) << 1);
            float b0 = bias[tn * 64 + d];
            float b1 = bias[tn * 64 + d + 1];
            out[row * DH + d]           = acc[im][in_][0] + b0;
            out[row * DH + d + 1]       = acc[im][in_][1] + b1;
            out[(row + 8) * DH + d]     = acc[im][in_][2] + b0;
            out[(row + 8) * DH + d + 1] = acc[im][in_][3] + b1;
        }
    }
}

// ---------------------------------------------------------------------------
// Kernel 2: flash attention per (head, q-tile of 128).
// 256 threads, 8 warps; each warp owns 16 q-rows.
// Q held in registers as pre-scaled tf32 A-fragments (loop invariant).
// Online softmax in m16n8k8 C-fragment layout with shfl row reductions.
// ---------------------------------------------------------------------------
#define SS_STRIDE 68
#define FLASH_SMEM_FLOATS (128 * SS_STRIDE + 64 * SS_STRIDE + 64 * SS_STRIDE)
#define FLASH_SMEM_BYTES  (FLASH_SMEM_FLOATS * 4)

__global__ __launch_bounds__(256) void flash_attn_kernel(float* __restrict__ out)
{
    extern __shared__ float sm[];
    float* Ss = sm;                     // [128][68]  scores / P (also Q staging)
    float* Ks = sm + 128 * SS_STRIDE;   // [64][68]   K tile [kv][d]
    float* Vs = Ks + 64 * SS_STRIDE;    // [64][68]   V tile [kv][d]

    const int h  = blockIdx.y;
    const int q0 = blockIdx.x * 128;

    const float* Qg = &g_QKV[0][h * S_LEN * DH];
    const float* Kg = &g_QKV[1][h * S_LEN * DH];
    const float* Vg = &g_QKV[2][h * S_LEN * DH];

    const int tid  = threadIdx.x;
    const int lane = tid & 31;
    const int warp = tid >> 5;
    const int wr0  = warp * 16;  // this warp's q-row base within tile

    // ---- Stage Q tile (scaled by 1/sqrt(dh)=0.125) through Ss, pull A-frags into regs
    #pragma unroll
    for (int i = 0; i < 8; i++) {
        int linear = tid + i * 256;            // 0..2047
        int r = linear >> 4, c4 = (linear & 15) << 2;
        float4 v = *reinterpret_cast<const float4*>(&Qg[(q0 + r) * DH + c4]);
        v.x *= 0.125f; v.y *= 0.125f; v.z *= 0.125f; v.w *= 0.125f;
        *reinterpret_cast<float4*>(&Ss[r * SS_STRIDE + c4]) = v;
    }
    __syncthreads();

    uint32_t qa[8][4];
    {
        int r0 = wr0 + (lane >> 2);
        #pragma unroll
        for (int f = 0; f < 8; f++) {
            int c0 = f * 8 + (lane & 3);
            qa[f][0] = f2tf32(Ss[r0 * SS_STRIDE + c0]);
            qa[f][1] = f2tf32(Ss[(r0 + 8) * SS_STRIDE + c0]);
            qa[f][2] = f2tf32(Ss[r0 * SS_STRIDE + c0 + 4]);
            qa[f][3] = f2tf32(Ss[(r0 + 8) * SS_STRIDE + c0 + 4]);
        }
    }

    float o[8][4];
    #pragma unroll
    for (int f = 0; f < 8; f++)
        #pragma unroll
        for (int k = 0; k < 4; k++) o[f][k] = 0.f;

    float m_lo = -1e30f, m_hi = -1e30f, l_lo = 0.f, l_hi = 0.f;

    for (int j = 0; j < S_LEN; j += 64) {
        __syncthreads();  // previous tile's smem reads done
        // ---- Load K/V tile 64x64 each (1024 float4 each)
        #pragma unroll
        for (int i = 0; i < 4; i++) {
            int linear = tid + i * 256;
            int r = linear >> 4, c4 = (linear & 15) << 2;
            *reinterpret_cast<float4*>(&Ks[r * SS_STRIDE + c4]) =
                *reinterpret_cast<const float4*>(&Kg[(j + r) * DH + c4]);
            *reinterpret_cast<float4*>(&Vs[r * SS_STRIDE + c4]) =
                *reinterpret_cast<const float4*>(&Vg[(j + r) * DH + c4]);
        }
        __syncthreads();

        // ---- S = (Q*scale) @ K^T   (16 x 64 per warp)
        float s[8][4];
        #pragma unroll
        for (int f = 0; f < 8; f++)
            #pragma unroll
            for (int k = 0; k < 4; k++) s[f][k] = 0.f;

        #pragma unroll
        for (int kk = 0; kk < 8; kk++) {   // d dimension, steps of 8
            int c0 = kk * 8 + (lane & 3);
            #pragma unroll
            for (int f = 0; f < 8; f++) {  // kv col fragment
                uint32_t b[2];
                int n0 = f * 8 + (lane >> 2);
                b[0] = f2tf32(Ks[n0 * SS_STRIDE + c0]);
                b[1] = f2tf32(Ks[n0 * SS_STRIDE + c0 + 4]);
                mma_tf32(s[f], qa[kk], b);
            }
        }

        // ---- Online softmax (rows lane/4 and lane/4+8 of this warp's 16)
        float tmax_lo = -1e30f, tmax_hi = -1e30f;
        #pragma unroll
        for (int f = 0; f < 8; f++) {
            tmax_lo = fmaxf(tmax_lo, fmaxf(s[f][0], s[f][1]));
            tmax_hi = fmaxf(tmax_hi, fmaxf(s[f][2], s[f][3]));
        }
        #pragma unroll
        for (int off = 1; off <= 2; off <<= 1) {
            tmax_lo = fmaxf(tmax_lo, __shfl_xor_sync(0xffffffffu, tmax_lo, off));
            tmax_hi = fmaxf(tmax_hi, __shfl_xor_sync(0xffffffffu, tmax_hi, off));
        }
        float mn_lo = fmaxf(m_lo, tmax_lo);
        float mn_hi = fmaxf(m_hi, tmax_hi);
        float alpha_lo = __expf(m_lo - mn_lo);
        float alpha_hi = __expf(m_hi - mn_hi);

        float sum_lo = 0.f, sum_hi = 0.f;
        #pragma unroll
        for (int f = 0; f < 8; f++) {
            s[f][0] = __expf(s[f][0] - mn_lo);
            s[f][1] = __expf(s[f][1] - mn_lo);
            s[f][2] = __expf(s[f][2] - mn_hi);
            s[f][3] = __expf(s[f][3] - mn_hi);
            sum_lo += s[f][0] + s[f][1];
            sum_hi += s[f][2] + s[f][3];
        }
        #pragma unroll
        for (int off = 1; off <= 2; off <<= 1) {
            sum_lo += __shfl_xor_sync(0xffffffffu, sum_lo, off);
            sum_hi += __shfl_xor_sync(0xffffffffu, sum_hi, off);
        }
        l_lo = l_lo * alpha_lo + sum_lo;
        l_hi = l_hi * alpha_hi + sum_hi;
        m_lo = mn_lo;
        m_hi = mn_hi;

        #pragma unroll
        for (int f = 0; f < 8; f++) {
            o[f][0] *= alpha_lo; o[f][1] *= alpha_lo;
            o[f][2] *= alpha_hi; o[f][3] *= alpha_hi;
        }

        // ---- Write P (warp-private rows) to Ss, reread as A-fragments
        {
            int r = wr0 + (lane >> 2);
            int cb = (lane & 3) << 1;
            #pragma unroll
            for (int f = 0; f < 8; f++) {
                Ss[r * SS_STRIDE + f * 8 + cb]           = s[f][0];
                Ss[r * SS_STRIDE + f * 8 + cb + 1]       = s[f][1];
                Ss[(r + 8) * SS_STRIDE + f * 8 + cb]     = s[f][2];
                Ss[(r + 8) * SS_STRIDE + f * 8 + cb + 1] = s[f][3];
            }
        }
        __syncwarp();

        // ---- O += P @ V
        #pragma unroll
        for (int kk = 0; kk < 8; kk++) {   // kv dimension, steps of 8
            uint32_t a[4];
            int r0 = wr0 + (lane >> 2);
            int c0 = kk * 8 + (lane & 3);
            a[0] = f2tf32(Ss[r0 * SS_STRIDE + c0]);
            a[1] = f2tf32(Ss[(r0 + 8) * SS_STRIDE + c0]);
            a[2] = f2tf32(Ss[r0 * SS_STRIDE + c0 + 4]);
            a[3] = f2tf32(Ss[(r0 + 8) * SS_STRIDE + c0 + 4]);
            #pragma unroll
            for (int f = 0; f < 8; f++) {  // dh fragment
                uint32_t b[2];
                int d0 = f * 8 + (lane >> 2);
                b[0] = f2tf32(Vs[(kk * 8 + (lane & 3)) * SS_STRIDE + d0]);
                b[1] = f2tf32(Vs[(kk * 8 + (lane & 3) + 4) * SS_STRIDE + d0]);
                mma_tf32(o[f], a, b);
            }
        }
    }

    // ---- Epilogue: normalize by l, write out[s][h*64+d]
    float inv_lo = 1.f / l_lo;
    float inv_hi = 1.f / l_hi;
    int row = q0 + wr0 + (lane >> 2);
    #pragma unroll
    for (int f = 0; f < 8; f++) {
        int d = f * 8 + ((lane & 3) << 1);
        int base_lo = row * HID + h * DH + d;
        int base_hi = (row + 8) * HID + h * DH + d;
        out[base_lo]     = o[f][0] * inv_lo;
        out[base_lo + 1] = o[f][1] * inv_lo;
        out[base_hi]     = o[f][2] * inv_hi;
        out[base_hi + 1] = o[f][3] * inv_hi;
    }
}

// ---------------------------------------------------------------------------
// Launch
// ---------------------------------------------------------------------------
extern "C" void kernel_launch(void* const* d_in, const int* in_sizes, int n_in,
                              void* d_out, int out_size)
{
    const float* x  = (const float*)d_in[0];
    const float* Wq = (const float*)d_in[1];
    const float* bq = (const float*)d_in[2];
    const float* Wk = (const float*)d_in[3];
    const float* bk = (const float*)d_in[4];
    const float* Wv = (const float*)d_in[5];
    const float* bv = (const float*)d_in[6];
    float* out = (float*)d_out;

    dim3 g1(S_LEN / 128, HID / 64, 3);   // 32 x 12 x 3
    qkv_gemm_kernel<<<g1, 256>>>(x, Wq, bq, Wk, bk, Wv, bv);

    cudaFuncSetAttribute(flash_attn_kernel,
                         cudaFuncAttributeMaxDynamicSharedMemorySize,
                         FLASH_SMEM_BYTES);
    dim3 g2(S_LEN / 128, NHEAD);         // 32 x 12
    flash_attn_kernel<<<g2, 256, FLASH_SMEM_BYTES>>>(out);
}